// round 7
// baseline (speedup 1.0000x reference)
#include <cuda_runtime.h>
#include <cstdint>

#define BB 4
#define CC 64
#define HH 256
#define WWID 512
#define MAXD 48
#define DD 97          // 2*MAXD+1
#define WT 128         // W tile per CTA
#define RW 224         // WT + 2*MAXD
#define NTHREADS 128
#define SMEM_BYTES ((CC*(WT+RW))*4)   // 90112 B

using u64 = unsigned long long;

__device__ __forceinline__ u64 pack2(unsigned lo, unsigned hi) {
    u64 d; asm("mov.b64 %0, {%1, %2};" : "=l"(d) : "r"(lo), "r"(hi)); return d;
}
__device__ __forceinline__ void unpack2(u64 v, unsigned &lo, unsigned &hi) {
    asm("mov.b64 {%0, %1}, %2;" : "=r"(lo), "=r"(hi) : "l"(v));
}
__device__ __forceinline__ void ffma2(u64 &acc, u64 a, u64 b) {
    asm("fma.rn.f32x2 %0, %1, %2, %0;" : "+l"(acc) : "l"(a), "l"(b));
}
__device__ __forceinline__ u64 mul2(u64 a, u64 b) {
    u64 d; asm("mul.rn.f32x2 %0, %1, %2;" : "=l"(d) : "l"(a), "l"(b)); return d;
}
__device__ __forceinline__ float lof(u64 v) { unsigned a,b; unpack2(v,a,b); return __uint_as_float(a); }
__device__ __forceinline__ float hif(u64 v) { unsigned a,b; unpack2(v,a,b); return __uint_as_float(b); }
__device__ __forceinline__ unsigned lou(u64 v){ unsigned a,b; unpack2(v,a,b); return a; }
__device__ __forceinline__ unsigned hiu(u64 v){ unsigned a,b; unpack2(v,a,b); return b; }

extern __shared__ float smem[];

// Load one channel's per-thread L (8 floats as 4 aligned pairs) and R span
// (20 floats as 10 aligned pairs) from smem. All even-offset pairs are native
// u64 register pairs from LDS.128 — zero packing MOVs.
__device__ __forceinline__ void load_c(const float* Lrow, const float* Rrow,
                                       int c, u64* L, u64* R)
{
    ulonglong2 a = *(const ulonglong2*)(Lrow + c * WT);
    ulonglong2 b = *(const ulonglong2*)(Lrow + c * WT + 4);
    L[0] = a.x; L[1] = a.y; L[2] = b.x; L[3] = b.y;
    #pragma unroll
    for (int k = 0; k < 5; k++) {
        ulonglong2 v = *(const ulonglong2*)(Rrow + c * RW + 4 * k);
        R[2 * k] = v.x; R[2 * k + 1] = v.y;
    }
}

struct Acc {
    u64   e[6][4];   // even jj: output pairs (2wp, 2wp+1)
    u64   o[6][3];   // odd  jj: output pairs (2p+1, 2p+2)
    float s[6][2];   // odd  jj: scalar ends w=0, w=7
};

// One channel of FFMA2 work. t = ww + 12 - jj.
// even jj=2jh:  pair k = wp + 6 - jh (even t -> native R pair)
// odd  jj=2jh+1: accumulator re-paired over (w odd, w even) so t even again:
//   pair k = p + 6 - jh ; scalars w=0 -> r[11-2jh] (hi of R[5-jh]),
//                          w=7 -> r[18-2jh] (lo of R[9-jh])
__device__ __forceinline__ void compute_c(Acc& A, const u64* L, const u64* R)
{
    u64 Lodd[3];
    Lodd[0] = pack2(hiu(L[0]), lou(L[1]));  // (l1,l2)
    Lodd[1] = pack2(hiu(L[1]), lou(L[2]));  // (l3,l4)
    Lodd[2] = pack2(hiu(L[2]), lou(L[3]));  // (l5,l6)
    float l0 = lof(L[0]);
    float l7 = hif(L[3]);
    #pragma unroll
    for (int jh = 0; jh < 6; jh++) {
        #pragma unroll
        for (int wp = 0; wp < 4; wp++)
            ffma2(A.e[jh][wp], L[wp], R[wp + 6 - jh]);
        #pragma unroll
        for (int p = 0; p < 3; p++)
            ffma2(A.o[jh][p], Lodd[p], R[p + 6 - jh]);
        A.s[jh][0] = fmaf(l0, hif(R[5 - jh]), A.s[jh][0]);
        A.s[jh][1] = fmaf(l7, lof(R[9 - jh]), A.s[jh][1]);
    }
}

__global__ void __launch_bounds__(NTHREADS, 2)
cost_volume_kernel(const float* __restrict__ Lg0,
                   const float* __restrict__ Rg0,
                   float* __restrict__ out)
{
    float* Ls = smem;              // [CC][WT]
    float* Rs = smem + CC * WT;    // [CC][RW], Rs[c][i] = r[w0-48+i]

    const int w0  = blockIdx.x * WT;
    const int h   = blockIdx.y;
    const int b   = blockIdx.z;
    const int tid = threadIdx.x;

    // ---------------- load L tile (coalesced float4) ----------------
    const float* Lg = Lg0 + ((size_t)(b * CC) * HH + h) * WWID + w0;
    {
        const int NV = CC * WT / 4;
        #pragma unroll 4
        for (int idx = tid; idx < NV; idx += NTHREADS) {
            int c = idx >> 5;
            int k = (idx & 31) << 2;
            float4 v = *(const float4*)(Lg + (size_t)c * HH * WWID + k);
            *(float4*)(Ls + c * WT + k) = v;
        }
    }
    // ---------------- load R tile with zero-padded halo ----------------
    const float* Rg = Rg0 + ((size_t)(b * CC) * HH + h) * WWID;
    {
        const int NV = CC * RW / 4;
        #pragma unroll 4
        for (int idx = tid; idx < NV; idx += NTHREADS) {
            int c = idx / 56;
            int k = (idx - c * 56) << 2;
            int gw = w0 - MAXD + k;
            const float* rr = Rg + (size_t)c * HH * WWID;
            float4 v;
            if (gw >= 0 && gw + 3 < WWID) {
                v = *(const float4*)(rr + gw);
            } else {
                v.x = (gw     >= 0 && gw     < WWID) ? rr[gw]     : 0.f;
                v.y = (gw + 1 >= 0 && gw + 1 < WWID) ? rr[gw + 1] : 0.f;
                v.z = (gw + 2 >= 0 && gw + 2 < WWID) ? rr[gw + 2] : 0.f;
                v.w = (gw + 3 >= 0 && gw + 3 < WWID) ? rr[gw + 3] : 0.f;
            }
            *(float4*)(Rs + c * RW + k) = v;
        }
    }
    __syncthreads();

    // ---------------- compute: 8(w) x 12(j) register tile per thread ------
    // td = tid&7 (j group), tw = tid>>3 (w group); j = 12*td + jj
    // Rs index i = w_local + 96 - j; per-thread span starts at
    // sA = 8*tw - 12*td + 84 (multiple of 4 -> aligned, conflict-free LDS.128)
    const int td = tid & 7;
    const int tw = tid >> 3;
    const int sA = 8 * tw - 12 * td + 84;

    Acc A;
    #pragma unroll
    for (int jh = 0; jh < 6; jh++) {
        #pragma unroll
        for (int wp = 0; wp < 4; wp++) A.e[jh][wp] = 0ULL;
        #pragma unroll
        for (int p = 0; p < 3; p++)  A.o[jh][p] = 0ULL;
        A.s[jh][0] = 0.f; A.s[jh][1] = 0.f;
    }

    const float* Lrow = Ls + 8 * tw;
    const float* Rrow = Rs + sA;

    // Software-pipelined c loop (double buffered: LDS of next c overlaps FFMAs)
    u64 LA[4], RA[10], LB[4], RB[10];
    load_c(Lrow, Rrow, 0, LA, RA);
    #pragma unroll 1
    for (int c = 0; c < CC; c += 2) {
        load_c(Lrow, Rrow, c + 1, LB, RB);
        compute_c(A, LA, RA);
        load_c(Lrow, Rrow, (c + 2) & (CC - 1), LA, RA);  // dummy wrap on last iter
        compute_c(A, LB, RB);
    }

    // ---------------- epilogue: scale by 1/64 and store -------------------
    const u64 scale2 = pack2(0x3C800000u, 0x3C800000u);  // (1/64, 1/64)
    const float scale = 0.015625f;
    float* outBase = out + (((size_t)b * DD) * HH + h) * WWID + w0 + 8 * tw;
    #pragma unroll
    for (int jh = 0; jh < 6; jh++) {
        // even jj = 2*jh
        {
            int j = 12 * td + 2 * jh;
            float* o = outBase + (size_t)j * HH * WWID;
            u64 v0 = mul2(A.e[jh][0], scale2), v1 = mul2(A.e[jh][1], scale2);
            *(uint4*)(o)     = make_uint4(lou(v0), hiu(v0), lou(v1), hiu(v1));
            u64 v2 = mul2(A.e[jh][2], scale2), v3 = mul2(A.e[jh][3], scale2);
            *(uint4*)(o + 4) = make_uint4(lou(v2), hiu(v2), lou(v3), hiu(v3));
        }
        // odd jj = 2*jh + 1: layout {s0, o0.lo, o0.hi, o1.lo | o1.hi, o2.lo, o2.hi, s7}
        {
            int j = 12 * td + 2 * jh + 1;
            float* o = outBase + (size_t)j * HH * WWID;
            u64 p0 = mul2(A.o[jh][0], scale2);
            u64 p1 = mul2(A.o[jh][1], scale2);
            u64 p2 = mul2(A.o[jh][2], scale2);
            float s0 = A.s[jh][0] * scale;
            float s7 = A.s[jh][1] * scale;
            *(uint4*)(o)     = make_uint4(__float_as_uint(s0), lou(p0), hiu(p0), lou(p1));
            *(uint4*)(o + 4) = make_uint4(hiu(p1), lou(p2), hiu(p2), __float_as_uint(s7));
        }
    }

    // ---------------- j = 96 plane (d = +48): i = w_local ------------------
    {
        float s = 0.f;
        #pragma unroll 8
        for (int c = 0; c < CC; c++)
            s += Ls[c * WT + tid] * Rs[c * RW + tid];
        out[(((size_t)b * DD + 96) * HH + h) * WWID + w0 + tid] = s * scale;
    }
}

extern "C" void kernel_launch(void* const* d_in, const int* in_sizes, int n_in,
                              void* d_out, int out_size)
{
    const float* L = (const float*)d_in[0];
    const float* R = (const float*)d_in[1];
    float* out = (float*)d_out;
    cudaFuncSetAttribute(cost_volume_kernel,
                         cudaFuncAttributeMaxDynamicSharedMemorySize, SMEM_BYTES);
    dim3 grid(WWID / WT, HH, BB);   // (4, 256, 4) = 4096 CTAs
    cost_volume_kernel<<<grid, NTHREADS, SMEM_BYTES>>>(L, R, out);
}